// round 17
// baseline (speedup 1.0000x reference)
#include <cuda_runtime.h>
#include <math.h>

#define BB 8
#define NPTS 2048
#define NPAIR 1024
#define NTHREADS 512
#define ROWS_PER_CTA 128          // dist: 16 warps * 8 rows
#define CHUNKS 16                 // dist/persist grid.x
#define NCH64 32                  // coarse chunks (dist kernel)
#define NCH16 128                 // fine chunks (persistent kernel)

// persistent kernel
#define PTHREADS 1024             // 32 warps * 4 rows = 128 rows/CTA
#define NCTAB 16                  // CTAs per batch (per-batch barrier scope)
#define PSTEPS 101                // 50*(f,g) + final f

// eps = 0.005
#define KLOG 288.53900817779268f
#define INV2K 0.0017328679513998633f
#define EPSLN2 0.0034657359027997266f
#define ACONST (-0.038123094930796993f)
#define SKIP_THR (-25.0f)

typedef unsigned long long u64;

__device__ __forceinline__ float ex2f(float x) {
    float r; asm("ex2.approx.ftz.f32 %0, %1;" : "=f"(r) : "f"(x)); return r;
}
__device__ __forceinline__ u64 pack2(float lo, float hi) {
    u64 r; asm("mov.b64 %0, {%1, %2};" : "=l"(r) : "f"(lo), "f"(hi)); return r;
}
__device__ __forceinline__ void unpack2(u64 v, float& lo, float& hi) {
    asm("mov.b64 {%0, %1}, %2;" : "=f"(lo), "=f"(hi) : "l"(v));
}
__device__ __forceinline__ u64 fma2(u64 a, u64 b, u64 c) {
    u64 r; asm("fma.rn.f32x2 %0, %1, %2, %3;" : "=l"(r) : "l"(a), "l"(b), "l"(c)); return r;
}
__device__ __forceinline__ u64 add2(u64 a, u64 b) {
    u64 r; asm("add.rn.f32x2 %0, %1, %2;" : "=l"(r) : "l"(a), "l"(b)); return r;
}

// Persistent scratch
__device__ float  g_p1[BB * NPTS * 3];
__device__ float  g_p2[BB * NPTS * 3];
__device__ float4 g_lo1[BB * NCH16], g_hi1[BB * NCH16];   // fine AABBs
__device__ float4 g_lo2[BB * NCH16], g_hi2[BB * NCH16];
__device__ float  g_f[BB * NPTS];
__device__ float  g_g[BB * NPTS];
__device__ float  g_partial[BB * CHUNKS];

// per-batch barrier state (generation counters survive graph replays)
__device__ int      g_bcnt[BB];
__device__ unsigned g_bgen[BB];

__device__ __forceinline__ void grid_bar(int b) {
    __syncthreads();
    if (threadIdx.x == 0) {
        __threadfence();
        int* cnt = &g_bcnt[b];
        unsigned* gen = &g_bgen[b];
        unsigned g0;
        asm volatile("ld.volatile.global.u32 %0, [%1];" : "=r"(g0) : "l"(gen));
        if (atomicAdd(cnt, 1) == NCTAB - 1) {
            asm volatile("st.volatile.global.u32 [%0], %1;" :: "l"(cnt), "r"(0));
            __threadfence();
            atomicAdd(gen, 1u);
        } else {
            unsigned cur;
            do {
                asm volatile("ld.volatile.global.u32 %0, [%1];" : "=r"(cur) : "l"(gen));
            } while (cur == g0);
        }
        __threadfence();
    }
    __syncthreads();
}

__global__ void init_kernel() {
    int i = blockIdx.x * blockDim.x + threadIdx.x;
    if (i < BB * NPTS) g_g[i] = 0.0f;
}

__device__ __forceinline__ unsigned expand_bits(unsigned v) {
    v &= 0x3FFu;
    v = (v | (v << 16)) & 0x030000FFu;
    v = (v | (v << 8))  & 0x0300F00Fu;
    v = (v | (v << 4))  & 0x030C30C3u;
    v = (v | (v << 2))  & 0x09249249u;
    return v;
}

// One CTA per batch: Morton bitonic sort + fine (16-pt) AABBs.
__global__ __launch_bounds__(NTHREADS, 1)
void sort_kernel(const float* __restrict__ pts, int side)
{
    __shared__ unsigned key[NPTS];
    __shared__ int      idx[NPTS];
    const int b = blockIdx.x, tid = threadIdx.x;
    const float* p = pts + b * NPTS * 3;

    for (int j = tid; j < NPTS; j += NTHREADS) {
        float x = p[3*j], y = p[3*j+1], z = p[3*j+2];
        unsigned qx = (unsigned)fminf(fmaxf(x * 1024.0f, 0.0f), 1023.0f);
        unsigned qy = (unsigned)fminf(fmaxf(y * 1024.0f, 0.0f), 1023.0f);
        unsigned qz = (unsigned)fminf(fmaxf(z * 1024.0f, 0.0f), 1023.0f);
        key[j] = expand_bits(qx) | (expand_bits(qy) << 1) | (expand_bits(qz) << 2);
        idx[j] = j;
    }
    __syncthreads();

    for (int k2 = 2; k2 <= NPTS; k2 <<= 1) {
        for (int j2 = k2 >> 1; j2 > 0; j2 >>= 1) {
            for (int i = tid; i < NPTS; i += NTHREADS) {
                int l = i ^ j2;
                if (l > i) {
                    bool up = ((i & k2) == 0);
                    unsigned ki = key[i], kl = key[l];
                    bool swp = up ? (ki > kl) : (ki < kl);
                    if (swp) {
                        key[i] = kl; key[l] = ki;
                        int t = idx[i]; idx[i] = idx[l]; idx[l] = t;
                    }
                }
            }
            __syncthreads();
        }
    }

    float* out = (side ? g_p2 : g_p1) + b * NPTS * 3;
    for (int k = tid; k < NPTS; k += NTHREADS) {
        int s = idx[k];
        out[3*k]   = p[3*s];
        out[3*k+1] = p[3*s+1];
        out[3*k+2] = p[3*s+2];
    }
    __syncthreads();

    if (tid < NCH16) {
        float lx = 1e30f, ly = 1e30f, lz = 1e30f;
        float hx = -1e30f, hy = -1e30f, hz = -1e30f;
        for (int k = 0; k < 16; k++) {
            int j = tid * 16 + k;
            float x = out[3*j], y = out[3*j+1], z = out[3*j+2];
            lx = fminf(lx, x); hx = fmaxf(hx, x);
            ly = fminf(ly, y); hy = fmaxf(hy, y);
            lz = fminf(lz, z); hz = fmaxf(hz, z);
        }
        float4* glo = side ? g_lo2 : g_lo1;
        float4* ghi = side ? g_hi2 : g_hi1;
        glo[b * NCH16 + tid] = make_float4(lx, ly, lz, 0.0f);
        ghi[b * NCH16 + tid] = make_float4(hx, hy, hz, 0.0f);
    }
}

// ---------- Persistent phase: all 101 half-steps, fine-chunk compaction ----------
// smem byte offsets (dynamic)
#define OFF_A2   0
#define OFF_B2   16384
#define OFF_A1   32768
#define OFF_B1   49152
#define OFF_YK2  65536
#define OFF_YK1  73728
#define OFF_BOX  81920      // loF2[128] hiF2[128] loF1[128] hiF1[128] (float4)
#define OFF_GM   90112      // float[128]
#define OFF_LIST 90624      // 32 warps * 136 bytes (132 entries area + int count)
#define OFF_MP   94976      // 32 warps * 8 floats  (mpf[4], mpg[4])
#define OFF_RBOX 96000      // 32 warps * 12 floats (dir0 box lo/hi, dir1 box lo/hi)
#define PSMEM    97536

__device__ __forceinline__ void half_step(
    char* sm, unsigned sAb, unsigned sBb, const float2* __restrict__ yk,
    const float4* __restrict__ boxLo, const float4* __restrict__ boxHi,
    const float* __restrict__ rbox,   // 6 floats: this warp, this dir
    float* __restrict__ mpS,          // 4 floats: this warp, this dir
    const float* __restrict__ colPot, float* __restrict__ outPot,
    const float* __restrict__ rowPts, int b, int row0)
{
    const int tid = threadIdx.x, warp = tid >> 5, lane = tid & 31;
    float* sGm = (float*)(sm + OFF_GM);
    unsigned char* sList = (unsigned char*)(sm + OFF_LIST) + warp * 136;
    int* sCnt = (int*)(sList + 132);

    // h update: one pair per thread; 8-lane groups reduce fine-chunk gmax.
    {
        float2 g2 = __ldcg((const float2*)(colPot + b * NPTS + 2 * tid));
        float2 y = yk[tid];
        float ha = fmaf(g2.x, KLOG, -y.x);
        float hb = fmaf(g2.y, KLOG, -y.y);
        asm volatile("st.shared.v2.f32 [%0], {%1,%2};"
                     :: "r"(sBb + (unsigned)tid * 16u + 8u), "f"(ha), "f"(hb));
        float gm = fmaxf(g2.x, g2.y);
        gm = fmaxf(gm, __shfl_xor_sync(0xffffffffu, gm, 4));
        gm = fmaxf(gm, __shfl_xor_sync(0xffffffffu, gm, 2));
        gm = fmaxf(gm, __shfl_xor_sync(0xffffffffu, gm, 1));
        if ((lane & 7) == 0) sGm[tid >> 3] = gm;
    }

    // prologue: row coefficients (global loads are warp-broadcast, L1-hot)
    const float* rp = rowPts + b * NPTS * 3;
    u64 X0b[4], X1b[4], X2b[4], negMb[4], Sp[4];
    float xx[4], mpr[4];
    #pragma unroll
    for (int r = 0; r < 4; r++) {
        int i = row0 + r;
        float x0 = rp[3*i], x1 = rp[3*i+1], x2 = rp[3*i+2];
        xx[r] = x0*x0 + x1*x1 + x2*x2;
        X0b[r] = pack2(2.0f*KLOG*x0, 2.0f*KLOG*x0);
        X1b[r] = pack2(2.0f*KLOG*x1, 2.0f*KLOG*x1);
        X2b[r] = pack2(2.0f*KLOG*x2, 2.0f*KLOG*x2);
        mpr[r] = mpS[r];
        negMb[r] = pack2(-mpr[r], -mpr[r]);
        Sp[r] = 0ull;
    }
    float tmax = fmaxf(fmaxf(KLOG*xx[0]-mpr[0], KLOG*xx[1]-mpr[1]),
                       fmaxf(KLOG*xx[2]-mpr[2], KLOG*xx[3]-mpr[3]));
    float rlx = rbox[0], rly = rbox[1], rlz = rbox[2];
    float rhx = rbox[3], rhy = rbox[4], rhz = rbox[5];

    __syncthreads();   // sGm + h writes visible to all warps

    // 128-bit fine-chunk activity mask -> compacted list
    unsigned bits[4];
    #pragma unroll
    for (int q = 0; q < 4; q++) {
        int c = lane + 32 * q;
        float4 lo = boxLo[c], hi = boxHi[c];
        float dx = fmaxf(fmaxf(lo.x - rhx, rlx - hi.x), 0.0f);
        float dy = fmaxf(fmaxf(lo.y - rhy, rly - hi.y), 0.0f);
        float dz = fmaxf(fmaxf(lo.z - rhz, rlz - hi.z), 0.0f);
        float d2 = dx*dx + dy*dy + dz*dz;
        float ub = KLOG * (sGm[c] - d2) + tmax;
        bits[q] = __ballot_sync(0xffffffffu, ub > SKIP_THR);
    }
    if (lane == 0) {
        int n = 0;
        #pragma unroll
        for (int q = 0; q < 4; q++) {
            unsigned mm = bits[q];
            while (mm) {
                int t = __ffs(mm) - 1;
                mm &= mm - 1;
                sList[n++] = (unsigned char)(q * 32 + t);
            }
        }
        while (n & 3) sList[n++] = 255;
        *sCnt = n;
    }
    __syncwarp();
    const int cnt = *sCnt;

    const int sub = lane >> 3, pin = lane & 7;
    for (int base = 0; base < cnt; base += 4) {
        int ci = sList[base + sub];
        bool dead = (ci == 255);
        unsigned off = (unsigned)((dead ? 0 : ci) * 128 + pin * 16);
        u64 y0p, y1p, y2p, hp;
        asm("ld.shared.v2.b64 {%0, %1}, [%2];" : "=l"(y0p), "=l"(y1p) : "r"(sAb + off));
        asm("ld.shared.v2.b64 {%0, %1}, [%2];" : "=l"(y2p), "=l"(hp)  : "r"(sBb + off));
        if (dead) hp = pack2(-1e30f, -1e30f);
        #pragma unroll
        for (int r = 0; r < 4; r++) {
            u64 hpr = add2(hp, negMb[r]);
            u64 w = fma2(X0b[r], y0p, fma2(X1b[r], y1p, fma2(X2b[r], y2p, hpr)));
            float wl, wh; unpack2(w, wl, wh);
            Sp[r] = add2(Sp[r], pack2(ex2f(wl), ex2f(wh)));
        }
    }

    #pragma unroll
    for (int r = 0; r < 4; r++) {
        float sl, sh; unpack2(Sp[r], sl, sh);
        float S = sl + sh;
        #pragma unroll
        for (int o = 16; o; o >>= 1)
            S += __shfl_xor_sync(0xffffffffu, S, o);
        float l2S = __log2f(fmaxf(S, 1e-38f));
        if (lane == 0) {
            outPot[b * NPTS + row0 + r] = ACONST - EPSLN2 * (mpr[r] + l2S) + xx[r];
            mpS[r] = mpr[r] + l2S;   // safe over-estimate of next row max
        }
    }
}

__global__ __launch_bounds__(PTHREADS, 1)
void sink_persist()
{
    extern __shared__ char sm[];
    float4* sA2 = (float4*)(sm + OFF_A2);
    float4* sB2 = (float4*)(sm + OFF_B2);
    float4* sA1 = (float4*)(sm + OFF_A1);
    float4* sB1 = (float4*)(sm + OFF_B1);
    float2* yk2 = (float2*)(sm + OFF_YK2);
    float2* yk1 = (float2*)(sm + OFF_YK1);
    float4* boxF = (float4*)(sm + OFF_BOX);   // [loF2|hiF2|loF1|hiF1] x 128
    float*  sMp  = (float*)(sm + OFF_MP);     // 32 warps x 8
    float*  sRb  = (float*)(sm + OFF_RBOX);   // 32 warps x 12

    const int b = blockIdx.y, tid = threadIdx.x;
    const int warp = tid >> 5, lane = tid & 31;

    if (tid < NCH16) {
        boxF[tid]            = g_lo2[b * NCH16 + tid];
        boxF[NCH16 + tid]    = g_hi2[b * NCH16 + tid];
        boxF[2*NCH16 + tid]  = g_lo1[b * NCH16 + tid];
        boxF[3*NCH16 + tid]  = g_hi1[b * NCH16 + tid];
    }
    // Static point tables (one pair per thread).
    {
        int j = 2 * tid;
        const float* c2 = g_p2 + b * NPTS * 3;
        float a0 = c2[3*j],   a1 = c2[3*j+1], a2 = c2[3*j+2];
        float b0 = c2[3*j+3], b1 = c2[3*j+4], b2 = c2[3*j+5];
        sA2[tid] = make_float4(a0, b0, a1, b1);
        sB2[tid] = make_float4(a2, b2, 0.0f, 0.0f);
        yk2[tid] = make_float2((a0*a0 + a1*a1 + a2*a2) * KLOG,
                               (b0*b0 + b1*b1 + b2*b2) * KLOG);
        const float* c1 = g_p1 + b * NPTS * 3;
        float c0 = c1[3*j],   cc1 = c1[3*j+1], c2v = c1[3*j+2];
        float d0 = c1[3*j+3], d1 = c1[3*j+4], d2v = c1[3*j+5];
        sA1[tid] = make_float4(c0, d0, cc1, d1);
        sB1[tid] = make_float4(c2v, d2v, 0.0f, 0.0f);
        yk1[tid] = make_float2((c0*c0 + cc1*cc1 + c2v*c2v) * KLOG,
                               (d0*d0 + d1*d1 + d2v*d2v) * KLOG);
    }

    // Stride-interleaved row-group assignment (load balance across CTAs).
    const int row0 = (warp * 16 + blockIdx.x) * 4;

    // Per-warp state init (lane 0): row boxes + analytic initial carried max.
    if (lane == 0) {
        #pragma unroll
        for (int d = 0; d < 2; d++) {
            const float* rp = (d == 0) ? (g_p1 + b * NPTS * 3) : (g_p2 + b * NPTS * 3);
            float lx = 1e30f, ly = 1e30f, lz = 1e30f;
            float hx = -1e30f, hy = -1e30f, hz = -1e30f;
            #pragma unroll
            for (int r = 0; r < 4; r++) {
                int i = row0 + r;
                float x0 = rp[3*i], x1 = rp[3*i+1], x2 = rp[3*i+2];
                lx = fminf(lx, x0); hx = fmaxf(hx, x0);
                ly = fminf(ly, x1); hy = fmaxf(hy, x1);
                lz = fminf(lz, x2); hz = fmaxf(hz, x2);
                sMp[warp * 8 + d * 4 + r] = (x0*x0 + x1*x1 + x2*x2) * KLOG;
            }
            float* rb = sRb + warp * 12 + d * 6;
            rb[0] = lx; rb[1] = ly; rb[2] = lz;
            rb[3] = hx; rb[4] = hy; rb[5] = hz;
        }
    }
    __syncthreads();

    const unsigned a2b = (unsigned)__cvta_generic_to_shared(sA2);
    const unsigned b2b = (unsigned)__cvta_generic_to_shared(sB2);
    const unsigned a1b = (unsigned)__cvta_generic_to_shared(sA1);
    const unsigned b1b = (unsigned)__cvta_generic_to_shared(sB1);

    #pragma unroll 1
    for (int s = 0; s < PSTEPS; s++) {
        if ((s & 1) == 0)
            half_step(sm, a2b, b2b, yk2, boxF, boxF + NCH16,
                      sRb + warp * 12, sMp + warp * 8,
                      g_g, g_f, g_p1, b, row0);
        else
            half_step(sm, a1b, b1b, yk1, boxF + 2*NCH16, boxF + 3*NCH16,
                      sRb + warp * 12 + 6, sMp + warp * 8 + 4,
                      g_f, g_g, g_p2, b, row0);
        if (s != PSTEPS - 1) grid_bar(b);
    }
}

// dist_i = N * sum_j 2^(K(f_i+g_j-C_ij)) * C_ij ; coarse chunk skip
__global__ __launch_bounds__(NTHREADS, 1)
void dist_kernel()
{
    __shared__ float4 sCol[NPTS];
    __shared__ float  sYY[NPTS];
    __shared__ float  sGm[64];
    __shared__ float4 sLo[NCH64], sHi[NCH64];
    __shared__ float  wsum[16];

    const int b = blockIdx.y, tid = threadIdx.x;
    const int warp = tid >> 5, lane = tid & 31;

    if (tid < NCH64) {
        float4 lo = g_lo2[b * NCH16 + 4*tid], hi = g_hi2[b * NCH16 + 4*tid];
        #pragma unroll
        for (int q = 1; q < 4; q++) {
            float4 l2 = g_lo2[b * NCH16 + 4*tid + q], h2 = g_hi2[b * NCH16 + 4*tid + q];
            lo.x = fminf(lo.x, l2.x); lo.y = fminf(lo.y, l2.y); lo.z = fminf(lo.z, l2.z);
            hi.x = fmaxf(hi.x, h2.x); hi.y = fmaxf(hi.y, h2.y); hi.z = fmaxf(hi.z, h2.z);
        }
        sLo[tid] = lo; sHi[tid] = hi;
    }

    const float* cp = g_p2 + b * NPTS * 3;
    #pragma unroll
    for (int k = 0; k < 4; k++) {
        int j = tid + k * NTHREADS;
        float gv = g_g[b * NPTS + j];
        float y0 = cp[3*j], y1 = cp[3*j+1], y2 = cp[3*j+2];
        float yy = y0*y0 + y1*y1 + y2*y2;
        sYY[j] = yy;
        sCol[j] = make_float4(y0, y1, y2, (gv - yy) * KLOG);
        float gm = gv;
        #pragma unroll
        for (int o = 16; o; o >>= 1)
            gm = fmaxf(gm, __shfl_xor_sync(0xffffffffu, gm, o));
        if (lane == 0) sGm[warp + k * 16] = gm;
    }
    __syncthreads();

    const int row0 = blockIdx.x * ROWS_PER_CTA + warp * 8;
    const float* rp = g_p1 + b * NPTS * 3;

    float X0[8], X1[8], X2[8], xx[8], cr[8], acc[8], fK[8];
    #pragma unroll
    for (int r = 0; r < 8; r++) {
        int i = row0 + r;
        float x0 = rp[3*i], x1 = rp[3*i+1], x2 = rp[3*i+2];
        xx[r] = x0*x0 + x1*x1 + x2*x2;
        X0[r] = 2.0f*KLOG*x0;
        X1[r] = 2.0f*KLOG*x1;
        X2[r] = 2.0f*KLOG*x2;
        float fv = g_f[b * NPTS + i];
        fK[r] = fv * KLOG;
        cr[r] = (fv - xx[r]) * KLOG;
        acc[r] = 0.0f;
    }

    unsigned mask;
    {
        float4 lo = sLo[lane], hi = sHi[lane];
        float gm = fmaxf(sGm[2 * lane], sGm[2 * lane + 1]);
        bool act = false;
        #pragma unroll
        for (int r = 0; r < 8; r++) {
            float x0 = X0[r] * INV2K, x1 = X1[r] * INV2K, x2 = X2[r] * INV2K;
            float dx = fmaxf(fmaxf(lo.x - x0, x0 - hi.x), 0.0f);
            float dy = fmaxf(fmaxf(lo.y - x1, x1 - hi.y), 0.0f);
            float dz = fmaxf(fmaxf(lo.z - x2, x2 - hi.z), 0.0f);
            float d2 = dx*dx + dy*dy + dz*dz;
            float ub = fK[r] + KLOG * (gm - d2);
            act |= (ub > SKIP_THR);
        }
        mask = __ballot_sync(0xffffffffu, act);
    }

    for (int c = 0; c < NCH64; c++) {
        if (!(mask & (1u << c))) continue;
        #pragma unroll
        for (int s = 0; s < 2; s++) {
            int j = c * 64 + s * 32 + lane;
            float4 col = sCol[j];
            float yy = sYY[j];
            #pragma unroll
            for (int r = 0; r < 8; r++) {
                float t = fmaf(X0[r], col.x, fmaf(X1[r], col.y, X2[r] * col.z));
                float p = ex2f(t + col.w + cr[r]);
                float C = fmaf(-EPSLN2, t, xx[r] + yy);
                acc[r] = fmaf(p, C, acc[r]);
            }
        }
    }
    #pragma unroll
    for (int r = 0; r < 8; r++) {
        #pragma unroll
        for (int o = 16; o; o >>= 1)
            acc[r] += __shfl_xor_sync(0xffffffffu, acc[r], o);
    }

    if (lane == 0) {
        float s = 0.0f;
        #pragma unroll
        for (int r = 0; r < 8; r++)
            s += sqrtf(fmaxf(acc[r] * (float)NPTS, 0.0f));
        wsum[warp] = s;
    }
    __syncthreads();
    if (tid == 0) {
        float s = 0.0f;
        #pragma unroll
        for (int w = 0; w < 16; w++) s += wsum[w];
        g_partial[b * CHUNKS + blockIdx.x] = s;
    }
}

__global__ void final_kernel(float* __restrict__ out) {
    __shared__ float s[BB * CHUNKS];
    int tid = threadIdx.x;
    s[tid] = g_partial[tid];
    __syncthreads();
    for (int o = (BB * CHUNKS) / 2; o; o >>= 1) {
        if (tid < o) s[tid] += s[tid + o];
        __syncthreads();
    }
    if (tid == 0) out[0] = s[0] * (1.0f / (BB * NPTS));
}

extern "C" void kernel_launch(void* const* d_in, const int* in_sizes, int n_in,
                              void* d_out, int out_size)
{
    const float* pcs1 = (const float*)d_in[0];
    const float* pcs2 = (const float*)d_in[1];
    float* out = (float*)d_out;

    static int smem_set = 0;
    if (!smem_set) {
        cudaFuncSetAttribute(sink_persist, cudaFuncAttributeMaxDynamicSharedMemorySize, PSMEM);
        smem_set = 1;
    }

    init_kernel<<<(BB * NPTS + NTHREADS - 1) / NTHREADS, NTHREADS>>>();
    sort_kernel<<<BB, NTHREADS>>>(pcs1, 0);
    sort_kernel<<<BB, NTHREADS>>>(pcs2, 1);

    sink_persist<<<dim3(CHUNKS, BB), PTHREADS, PSMEM>>>();

    dist_kernel<<<dim3(CHUNKS, BB), NTHREADS>>>();
    final_kernel<<<1, BB * CHUNKS>>>(out);
}